// round 13
// baseline (speedup 1.0000x reference)
#include <cuda_runtime.h>
#include <cuda_fp16.h>
#include <stdint.h>
#include <math.h>

// Problem dims
#define NB   32
#define NT   512
#define ND   1024
#define NH   1024
#define NG   4096
#define MTOT (NB * NT)
#define NCTA 128
#define NTHR 512
#define HSEQ ((size_t)NB * NT * NH)

// Scratch (allocation-free rule: __device__ globals)
__device__ unsigned g_barrier;
__device__ __half g_xh[(size_t)MTOT * ND];   // x hi (fp16), [b*NT+t][k]
__device__ __half g_xl[(size_t)MTOT * ND];   // x lo (fp16 residual)
__device__ __half g_hh[NB * NH];             // h hi (per step)
__device__ __half g_hl[NB * NH];             // h lo

// persistent-kernel smem byte offsets
//   whh/wih resident fp16 [1024][40] (row 80 B = 5x16: aligned, conflict-free)
//   staging: 2 buffers of 33792 B (256-k chunk of split activations:
//            hi [32][264] fp16, row 528 B = 33x16, then lo at +16896)
//   red (16 x 576 fl = 36864 B) aliases staging; gb (4352 B) at +40960
#define WHH_B  0
#define WIH_B  81920
#define SCR_B  163840
#define HBUF_STRIDE_B 33792
#define HROW_B 528
#define HLO_OFF 16896
#define GB_B   (SCR_B + 40960)
#define PERSIST_SMEM 231424

// ---------------------------------------------------------------------------
// helpers
// ---------------------------------------------------------------------------
__device__ __forceinline__ unsigned ld_acq(const unsigned* p) {
    unsigned v;
    asm volatile("ld.acquire.gpu.u32 %0, [%1];" : "=r"(v) : "l"(p) : "memory");
    return v;
}

__device__ __forceinline__ void red_release_add(unsigned* p, unsigned v) {
    asm volatile("red.release.gpu.global.add.u32 [%0], %1;"
                 :: "l"(p), "r"(v) : "memory");
}

__device__ __forceinline__ float sigmoidf_(float x) {
    return 1.0f / (1.0f + __expf(-x));
}

__device__ __forceinline__ float tanh_fast(float x) {
    float a = fabsf(x);
    float e = __expf(-2.0f * a);
    float r = (1.0f - e) / (1.0f + e);
    return copysignf(r, x);
}

__device__ __forceinline__ uint32_t smem_u32(const void* p) {
    uint32_t a;
    asm("{ .reg .u64 t; cvta.to.shared.u64 t, %1; cvt.u32.u64 %0, t; }"
        : "=r"(a) : "l"(p));
    return a;
}

__device__ __forceinline__ void cpa16_cg(uint32_t dst, const void* src) {
    asm volatile("cp.async.cg.shared.global [%0], [%1], 16;"
                 :: "r"(dst), "l"(src));
}

__device__ __forceinline__ void cp_commit() {
    asm volatile("cp.async.commit_group;");
}

template <int N>
__device__ __forceinline__ void cp_wait() {
    asm volatile("cp.async.wait_group %0;" :: "n"(N));
}

__device__ __forceinline__ void ldm_x4(uint32_t* r, uint32_t addr) {
    asm volatile("ldmatrix.sync.aligned.m8n8.x4.shared.b16 {%0,%1,%2,%3}, [%4];"
                 : "=r"(r[0]), "=r"(r[1]), "=r"(r[2]), "=r"(r[3]) : "r"(addr));
}

__device__ __forceinline__ void ldm_x4_t(uint32_t* r, uint32_t addr) {
    asm volatile("ldmatrix.sync.aligned.m8n8.x4.trans.shared.b16 {%0,%1,%2,%3}, [%4];"
                 : "=r"(r[0]), "=r"(r[1]), "=r"(r[2]), "=r"(r[3]) : "r"(addr));
}

__device__ __forceinline__ void mma_f16(float* d, const uint32_t* a,
                                        const uint32_t* b) {
    asm volatile(
        "mma.sync.aligned.m16n8k16.row.col.f32.f16.f16.f32 "
        "{%0,%1,%2,%3}, {%4,%5,%6,%7}, {%8,%9}, {%0,%1,%2,%3};"
        : "+f"(d[0]), "+f"(d[1]), "+f"(d[2]), "+f"(d[3])
        : "r"(a[0]), "r"(a[1]), "r"(a[2]), "r"(a[3]), "r"(b[0]), "r"(b[1]));
}

// ---------------------------------------------------------------------------
__global__ void init_bar_kernel() {
    if (threadIdx.x == 0) g_barrier = 0u;
}

// ---------------------------------------------------------------------------
// split x into fp16 hi + fp16 residual
// ---------------------------------------------------------------------------
__global__ __launch_bounds__(256) void split_x_kernel(const float* __restrict__ x) {
    size_t i = (size_t)blockIdx.x * blockDim.x + threadIdx.x;
    if (i < (size_t)MTOT * ND) {
        float a = x[i];
        __half h = __float2half(a);
        g_xh[i] = h;
        g_xl[i] = __float2half(a - __half2float(h));
    }
}

// ---------------------------------------------------------------------------
// stage one 256-k chunk of split activations into smem (cg = bypass L1).
// For c < 4: h[t-1] chunks; for c >= 4: x[:, t, :] chunks.
// Buffer layout: hi [32][264] fp16 (row 528 B), lo at +16896.
// ---------------------------------------------------------------------------
__device__ __forceinline__ void stage_chunk(uint32_t hbuf, int c, int t, int tid) {
    int row = tid >> 4;          // 0..31 (batch)
    int seg = tid & 15;          // thread covers segs {seg, seg+16} per half
    const __half* srcH;
    const __half* srcL;
    if (c < 4) {
        size_t off = (size_t)row * NH + c * 256 + seg * 8;
        srcH = g_hh + off;
        srcL = g_hl + off;
    } else {
        size_t off = (size_t)row * ((size_t)NT * ND) + (size_t)t * ND +
                     (c - 4) * 256 + seg * 8;
        srcH = g_xh + off;
        srcL = g_xl + off;
    }
    uint32_t d = hbuf + row * HROW_B + seg * 16;
    cpa16_cg(d, srcH);
    cpa16_cg(d + 256, srcH + 128);
    cpa16_cg(d + HLO_OFF, srcL);
    cpa16_cg(d + HLO_OFF + 256, srcL + 128);
}

// ---------------------------------------------------------------------------
// per-warp compute for one 256-k chunk: warp = (ks 0..7: k32 slice,
// ch 0..1: col half). 2-term: (ah + al) . w16
// ---------------------------------------------------------------------------
__device__ __forceinline__ void rec_compute(uint32_t hbuf, uint32_t wbase,
                                            int kc, int ks, int ch,
                                            int lane, float acc[2][2][4]) {
    for (int sub = 0; sub < 2; sub++) {
        uint32_t ahh[2][4], ahl[2][4], bw[4];
        for (int mt = 0; mt < 2; mt++) {
            uint32_t ad = hbuf + (mt * 16 + (lane & 15)) * HROW_B +
                          ks * 64 + sub * 32 + (lane >> 4) * 16;
            ldm_x4(ahh[mt], ad);
            ldm_x4(ahl[mt], ad + HLO_OFF);
        }
        {
            uint32_t krow = kc * 256 + ks * 32 + sub * 16 + (lane & 15);
            uint32_t coff = ch * 32 + (lane >> 4) * 16;
            ldm_x4_t(bw, wbase + krow * 80 + coff);
        }
        for (int mt = 0; mt < 2; mt++) {
            mma_f16(acc[mt][0], ahh[mt], &bw[0]);
            mma_f16(acc[mt][1], ahh[mt], &bw[2]);
            mma_f16(acc[mt][0], ahl[mt], &bw[0]);
            mma_f16(acc[mt][1], ahl[mt], &bw[2]);
        }
    }
}

// write warp partials: red[w][row 32][col 16 (+2 pad)]
__device__ __forceinline__ void write_partials(float* red, int wid, int lane,
                                               const float acc[2][2][4]) {
    float* rw = red + wid * 576;
    for (int mt = 0; mt < 2; mt++) {
        for (int nt = 0; nt < 2; nt++) {
            int row = mt * 16 + (lane >> 2);
            int col = nt * 8 + (lane & 3) * 2;
            *(float2*)&rw[row * 18 + col] =
                make_float2(acc[mt][nt][0], acc[mt][nt][1]);
            *(float2*)&rw[(row + 8) * 18 + col] =
                make_float2(acc[mt][nt][2], acc[mt][nt][3]);
        }
    }
}

// ---------------------------------------------------------------------------
// Persistent fused LSTM: per step, gates = x_t @ Wih + h_{t-1} @ Whh + bias.
// Both W slices SMEM-resident as fp16. 8 K-chunks/step (4 h + 4 x),
// double-buffered cp.async staging; software grid barrier between steps.
// ---------------------------------------------------------------------------
__global__ __launch_bounds__(NTHR, 1)
void lstm_persist(const float* __restrict__ Wih, const float* __restrict__ Whh,
                  const float* __restrict__ bias, float* __restrict__ out,
                  int write_final) {
    extern __shared__ __align__(16) char smx[];
    __half* whh = (__half*)(smx + WHH_B);
    __half* wih = (__half*)(smx + WIH_B);
    float* red = (float*)(smx + SCR_B);
    float* gb  = (float*)(smx + GB_B);
    const uint32_t sm0 = smem_u32(smx);
    const uint32_t whh_a = sm0 + WHH_B;
    const uint32_t wih_a = sm0 + WIH_B;
    const uint32_t scr_a = sm0 + SCR_B;

    const int tid = threadIdx.x;
    const int wid = tid >> 5;
    const int lane = tid & 31;
    const int base = (int)blockIdx.x * 8;
    const int ks = wid & 7;
    const int ch = wid >> 3;

    // preload both W slices as fp16 [k][40] (cols 0..31 used)
    for (int it = 0; it < 64; it++) {
        int idx = tid + it * NTHR;        // 0..32767
        int k = idx >> 5;
        int col = idx & 31;
        size_t goff = (size_t)k * NG + (col >> 3) * NH + base + (col & 7);
        whh[k * 40 + col] = __float2half(Whh[goff]);
        wih[k * 40 + col] = __float2half(Wih[goff]);
    }

    // bias registers for epilogue threads
    float bias_r[4];
    if (tid < 256) {
        int jj = tid & 7;
        for (int g = 0; g < 4; g++) {
            bias_r[g] = bias[g * NH + base + jj];
        }
    }

    float c_reg = 0.0f;
    unsigned bar_tgt = 0;

    __syncthreads();

    for (int t = 0; t < NT; t++) {
        float acc[2][2][4];
        for (int mt = 0; mt < 2; mt++)
            for (int nt = 0; nt < 2; nt++)
                for (int r = 0; r < 4; r++)
                    acc[mt][nt][r] = 0.0f;

        const int cs = (t > 0) ? 0 : 4;   // t=0: x chunks only (h0 = 0)

        stage_chunk(scr_a + (cs & 1) * HBUF_STRIDE_B, cs, t, tid);
        cp_commit();

        for (int c = cs; c < 8; c++) {
            if (c < 7) {
                stage_chunk(scr_a + ((c + 1) & 1) * HBUF_STRIDE_B, c + 1, t, tid);
                cp_commit();
                cp_wait<1>();
            } else {
                cp_wait<0>();
            }
            __syncthreads();
            rec_compute(scr_a + (c & 1) * HBUF_STRIDE_B,
                        (c < 4) ? whh_a : wih_a, c & 3, ks, ch, lane, acc);
            __syncthreads();
        }

        // partials -> red (aliases staging; compute synced above)
        write_partials(red, wid, lane, acc);
        __syncthreads();

        // reduce 8 partials per col-half; thread (b = tid&31, cp = tid>>5)
        {
            int b = tid & 31;
            int cp = tid >> 5;               // 0..15 -> cols 2cp, 2cp+1
            int half = cp >> 3;
            float2 s = make_float2(0.0f, 0.0f);
            for (int w = 0; w < 8; w++) {
                float2 v = *(float2*)&red[(half * 8 + w) * 576 + b * 18 +
                                          ((cp * 2) & 15)];
                s.x += v.x;
                s.y += v.y;
            }
            gb[(cp * 2) * 34 + b] = s.x;
            gb[(cp * 2 + 1) * 34 + b] = s.y;
        }
        __syncthreads();

        // epilogue: thread (b, jj); c in register; write h fp32 + fp16 split
        if (tid < 256) {
            const int b = tid >> 3;
            const int jj = tid & 7;
            float gate[4];
            for (int g = 0; g < 4; g++) {
                gate[g] = gb[(g * 8 + jj) * 34 + b] + bias_r[g];
            }
            float ig = sigmoidf_(gate[0]);
            float fg = sigmoidf_(gate[1]);
            float gg = tanh_fast(gate[2]);
            float og = sigmoidf_(gate[3]);
            c_reg = fg * c_reg + ig * gg;
            float h = og * tanh_fast(c_reg);
            out[((size_t)b * NT + t) * NH + base + jj] = h;
            __half hh = __float2half(h);
            g_hh[b * NH + base + jj] = hh;
            g_hl[b * NH + base + jj] = __float2half(h - __half2float(hh));
            if (write_final && t == NT - 1) {
                out[HSEQ + (size_t)b * NH + base + jj] = h;
                out[HSEQ + (size_t)(NB * NH) + (size_t)b * NH + base + jj] = c_reg;
            }
        }

        // grid barrier (release/acquire; skip after last step)
        if (t < NT - 1) {
            __syncthreads();
            bar_tgt += NCTA;
            if (tid == 0) {
                red_release_add(&g_barrier, 1u);
                while (ld_acq(&g_barrier) < bar_tgt) { }
            }
            __syncthreads();
        }
    }
}

// ---------------------------------------------------------------------------
// launch
// ---------------------------------------------------------------------------
extern "C" void kernel_launch(void* const* d_in, const int* in_sizes, int n_in,
                              void* d_out, int out_size) {
    const float* x = (const float*)d_in[0];
    const float* wih = (const float*)d_in[1];
    const float* whh = (const float*)d_in[2];
    const float* bias = (const float*)d_in[3];
    float* out = (float*)d_out;

    (void)in_sizes;
    (void)n_in;

    cudaFuncSetAttribute(lstm_persist,
                         cudaFuncAttributeMaxDynamicSharedMemorySize,
                         PERSIST_SMEM);

    init_bar_kernel<<<1, 32>>>();

    split_x_kernel<<<((size_t)MTOT * ND) / 256, 256>>>(x);

    int wf = (out_size >= (int)(HSEQ + 2 * NB * NH)) ? 1 : 0;
    lstm_persist<<<NCTA, NTHR, PERSIST_SMEM>>>(wih, whh, bias, out, wf);
}

// round 14
// speedup vs baseline: 1.3018x; 1.3018x over previous
#include <cuda_runtime.h>
#include <cuda_fp16.h>
#include <stdint.h>
#include <math.h>

// Problem dims
#define NB   32
#define NT   512
#define ND   1024
#define NH   1024
#define NG   4096
#define MTOT (NB * NT)
#define NCTA 128
#define NTHR 512
#define HSEQ ((size_t)NB * NT * NH)

// Scratch (allocation-free rule: __device__ globals)
__device__ float g_xproj[(size_t)MTOT * NG];            // 256 MB
__device__ unsigned g_barrier;
__device__ __half g_ah[(size_t)MTOT * ND];              // x hi  [m][k]
__device__ __half g_al[(size_t)MTOT * ND];              // x lo  [m][k]
__device__ __half g_bh[(size_t)ND * NG];                // wih fp16 [k][n]
__device__ __half g_hh[NB * NH];                        // h hi (per step)
__device__ __half g_hl[NB * NH];                        // h lo

// mma GEMM tile config (xproj): A hi/lo split fp16, B single fp16
#define A_STRIDE 40
#define B_STRIDE 136
#define A_BUF_B (128 * A_STRIDE * 2)          // 10240
#define B_BUF_B (32 * B_STRIDE * 2)           // 8704
#define BUF_B   (2 * A_BUF_B + B_BUF_B)       // 29184
#define GEMM_SMEM (2 * BUF_B)                 // 58368

// persistent-kernel smem byte offsets
//   whh resident fp16 [1024][40] (row 80 B = 5x16: aligned, conflict-free)
//   staging: 2 buffers of 33792 B (256-k chunk of split h:
//            hi [32][264] fp16, row 528 B = 33x16, then lo at +16896)
//   red (16 x 576 fl = 36864 B) aliases staging; gb (4352 B) disjoint
#define WHH_B  0
#define SCR_B  81920
#define HBUF_STRIDE_B 33792
#define HROW_B 528
#define HLO_OFF 16896
#define GB_B   (SCR_B + 40960)
#define PERSIST_SMEM 149504

// ---------------------------------------------------------------------------
// helpers
// ---------------------------------------------------------------------------
__device__ __forceinline__ unsigned ld_acq(const unsigned* p) {
    unsigned v;
    asm volatile("ld.acquire.gpu.u32 %0, [%1];" : "=r"(v) : "l"(p) : "memory");
    return v;
}

__device__ __forceinline__ void red_release_add(unsigned* p, unsigned v) {
    asm volatile("red.release.gpu.global.add.u32 [%0], %1;"
                 :: "l"(p), "r"(v) : "memory");
}

__device__ __forceinline__ float sigmoidf_(float x) {
    return 1.0f / (1.0f + __expf(-x));
}

__device__ __forceinline__ float tanh_fast(float x) {
    float a = fabsf(x);
    float e = __expf(-2.0f * a);
    float r = (1.0f - e) / (1.0f + e);
    return copysignf(r, x);
}

__device__ __forceinline__ uint32_t smem_u32(const void* p) {
    uint32_t a;
    asm("{ .reg .u64 t; cvta.to.shared.u64 t, %1; cvt.u32.u64 %0, t; }"
        : "=r"(a) : "l"(p));
    return a;
}

__device__ __forceinline__ void cpa16(uint32_t dst, const void* src) {
    asm volatile("cp.async.ca.shared.global [%0], [%1], 16;"
                 :: "r"(dst), "l"(src));
}

__device__ __forceinline__ void cpa16_cg(uint32_t dst, const void* src) {
    asm volatile("cp.async.cg.shared.global [%0], [%1], 16;"
                 :: "r"(dst), "l"(src));
}

__device__ __forceinline__ void cp_commit() {
    asm volatile("cp.async.commit_group;");
}

template <int N>
__device__ __forceinline__ void cp_wait() {
    asm volatile("cp.async.wait_group %0;" :: "n"(N));
}

__device__ __forceinline__ void ldm_x4(uint32_t* r, uint32_t addr) {
    asm volatile("ldmatrix.sync.aligned.m8n8.x4.shared.b16 {%0,%1,%2,%3}, [%4];"
                 : "=r"(r[0]), "=r"(r[1]), "=r"(r[2]), "=r"(r[3]) : "r"(addr));
}

__device__ __forceinline__ void ldm_x4_t(uint32_t* r, uint32_t addr) {
    asm volatile("ldmatrix.sync.aligned.m8n8.x4.trans.shared.b16 {%0,%1,%2,%3}, [%4];"
                 : "=r"(r[0]), "=r"(r[1]), "=r"(r[2]), "=r"(r[3]) : "r"(addr));
}

__device__ __forceinline__ void mma_f16(float* d, const uint32_t* a,
                                        const uint32_t* b) {
    asm volatile(
        "mma.sync.aligned.m16n8k16.row.col.f32.f16.f16.f32 "
        "{%0,%1,%2,%3}, {%4,%5,%6,%7}, {%8,%9}, {%0,%1,%2,%3};"
        : "+f"(d[0]), "+f"(d[1]), "+f"(d[2]), "+f"(d[3])
        : "r"(a[0]), "r"(a[1]), "r"(a[2]), "r"(a[3]), "r"(b[0]), "r"(b[1]));
}

// ---------------------------------------------------------------------------
__global__ void init_bar_kernel() {
    if (threadIdx.x == 0) g_barrier = 0u;
}

// ---------------------------------------------------------------------------
// split: x -> fp16 hi + fp16 residual; wih -> single fp16 [k][n]
// ---------------------------------------------------------------------------
__global__ __launch_bounds__(256) void split_kernel(const float* __restrict__ x,
                                                    const float* __restrict__ wih) {
    size_t i = (size_t)blockIdx.x * blockDim.x + threadIdx.x;
    if (i < (size_t)MTOT * ND) {
        float a = x[i];
        __half h = __float2half(a);
        g_ah[i] = h;
        g_al[i] = __float2half(a - __half2float(h));
    }
    if (i < (size_t)ND * NG) {
        g_bh[i] = __float2half(wih[i]);
    }
}

// ---------------------------------------------------------------------------
// x_proj = x @ W_ih + bias via fp16 mma.sync, 2-term (ah + al) . w16
// ---------------------------------------------------------------------------
__device__ __forceinline__ void stage_chunk(uint32_t sbuf, int kc, int rowBase,
                                            int colBase, int tid) {
    for (int i = 0; i < 2; i++) {
        int idx = tid + i * 256;
        int row = idx >> 2;
        int c4 = idx & 3;
        size_t goff = (size_t)(rowBase + row) * ND + kc * 32 + c4 * 8;
        uint32_t d = sbuf + row * (A_STRIDE * 2) + c4 * 16;
        cpa16(d, g_ah + goff);
        cpa16(d + A_BUF_B, g_al + goff);
    }
    for (int i = 0; i < 2; i++) {
        int idx = tid + i * 256;
        int row = idx >> 4;
        int c16 = idx & 15;
        size_t goff = (size_t)(kc * 32 + row) * NG + colBase + c16 * 8;
        uint32_t d = sbuf + 2 * A_BUF_B + row * (B_STRIDE * 2) + c16 * 16;
        cpa16(d, g_bh + goff);
    }
}

__global__ __launch_bounds__(256) void mma_xproj(const float* __restrict__ bias) {
    extern __shared__ __align__(16) char gsm[];
    const uint32_t sb0 = smem_u32(gsm);

    const int tid = threadIdx.x;
    const int lane = tid & 31;
    const int wid = tid >> 5;
    const int warp_m = wid >> 2;
    const int warp_n = wid & 3;
    const int rowBase = blockIdx.y * 128;
    const int colBase = blockIdx.x * 128;

    float acc[4][4][4];
    for (int mt = 0; mt < 4; mt++)
        for (int nt = 0; nt < 4; nt++)
            for (int r = 0; r < 4; r++)
                acc[mt][nt][r] = 0.0f;

    stage_chunk(sb0, 0, rowBase, colBase, tid);
    cp_commit();

    for (int c = 0; c < 32; c++) {
        if (c < 31) {
            stage_chunk(sb0 + ((c + 1) & 1) * BUF_B, c + 1, rowBase, colBase, tid);
            cp_commit();
            cp_wait<1>();
        } else {
            cp_wait<0>();
        }
        __syncthreads();

        const uint32_t sb = sb0 + (c & 1) * BUF_B;
        for (int ks = 0; ks < 2; ks++) {
            uint32_t ah[4][4], al[4][4], bh[2][4];
            for (int mt = 0; mt < 4; mt++) {
                uint32_t ad = sb +
                    (warp_m * 64 + mt * 16 + (lane & 15)) * (A_STRIDE * 2) +
                    ks * 32 + (lane >> 4) * 16;
                ldm_x4(ah[mt], ad);
                ldm_x4(al[mt], ad + A_BUF_B);
            }
            for (int np = 0; np < 2; np++) {
                uint32_t bd = sb + 2 * A_BUF_B +
                    (ks * 16 + (lane & 15)) * (B_STRIDE * 2) +
                    (warp_n * 32 + np * 16 + (lane >> 4) * 8) * 2;
                ldm_x4_t(bh[np], bd);
            }
            for (int mt = 0; mt < 4; mt++) {
                for (int np = 0; np < 2; np++) {
                    mma_f16(acc[mt][2 * np],     ah[mt], &bh[np][0]);
                    mma_f16(acc[mt][2 * np + 1], ah[mt], &bh[np][2]);
                    mma_f16(acc[mt][2 * np],     al[mt], &bh[np][0]);
                    mma_f16(acc[mt][2 * np + 1], al[mt], &bh[np][2]);
                }
            }
        }
        __syncthreads();
    }

    for (int mt = 0; mt < 4; mt++) {
        for (int nt = 0; nt < 4; nt++) {
            int row = rowBase + warp_m * 64 + mt * 16 + (lane >> 2);
            int col = colBase + warp_n * 32 + nt * 8 + (lane & 3) * 2;
            float b0 = bias[col];
            float b1 = bias[col + 1];
            float2 v0 = make_float2(acc[mt][nt][0] + b0, acc[mt][nt][1] + b1);
            float2 v1 = make_float2(acc[mt][nt][2] + b0, acc[mt][nt][3] + b1);
            *(float2*)&g_xproj[(size_t)row * NG + col] = v0;
            *(float2*)&g_xproj[(size_t)(row + 8) * NG + col] = v1;
        }
    }
}

// ---------------------------------------------------------------------------
// recurrence staging: one 256-k chunk of split h (cg = bypass L1)
// buffer: hi [32][264] fp16 (row 528 B), lo at +16896
// ---------------------------------------------------------------------------
__device__ __forceinline__ void stage_h_chunk(uint32_t hbuf, int c, int tid) {
    int row = tid >> 4;
    int seg = tid & 15;
    const __half* srch = g_hh + row * NH + c * 256 + seg * 8;
    const __half* srcl = g_hl + row * NH + c * 256 + seg * 8;
    uint32_t d = hbuf + row * HROW_B + seg * 16;
    cpa16_cg(d, srch);
    cpa16_cg(d + 256, srch + 128);
    cpa16_cg(d + HLO_OFF, srcl);
    cpa16_cg(d + HLO_OFF + 256, srcl + 128);
}

// per-warp compute for one 256-k chunk: warp = (ks 0..7: k32 slice,
// ch 0..1: col half). 2-term: (hh + hl) . w16
__device__ __forceinline__ void rec_compute(uint32_t hbuf, uint32_t wbase,
                                            int kc, int ks, int ch,
                                            int lane, float acc[2][2][4]) {
    for (int sub = 0; sub < 2; sub++) {
        uint32_t ahh[2][4], ahl[2][4], bw[4];
        for (int mt = 0; mt < 2; mt++) {
            uint32_t ad = hbuf + (mt * 16 + (lane & 15)) * HROW_B +
                          ks * 64 + sub * 32 + (lane >> 4) * 16;
            ldm_x4(ahh[mt], ad);
            ldm_x4(ahl[mt], ad + HLO_OFF);
        }
        {
            uint32_t krow = kc * 256 + ks * 32 + sub * 16 + (lane & 15);
            uint32_t coff = ch * 32 + (lane >> 4) * 16;
            ldm_x4_t(bw, wbase + krow * 80 + coff);
        }
        for (int mt = 0; mt < 2; mt++) {
            mma_f16(acc[mt][0], ahh[mt], &bw[0]);
            mma_f16(acc[mt][1], ahh[mt], &bw[2]);
            mma_f16(acc[mt][0], ahl[mt], &bw[0]);
            mma_f16(acc[mt][1], ahl[mt], &bw[2]);
        }
    }
}

// write warp partials: red[w][row 32][col 16 (+2 pad)]
__device__ __forceinline__ void write_partials(float* red, int wid, int lane,
                                               const float acc[2][2][4]) {
    float* rw = red + wid * 576;
    for (int mt = 0; mt < 2; mt++) {
        for (int nt = 0; nt < 2; nt++) {
            int row = mt * 16 + (lane >> 2);
            int col = nt * 8 + (lane & 3) * 2;
            *(float2*)&rw[row * 18 + col] =
                make_float2(acc[mt][nt][0], acc[mt][nt][1]);
            *(float2*)&rw[(row + 8) * 18 + col] =
                make_float2(acc[mt][nt][2], acc[mt][nt][3]);
        }
    }
}

// ---------------------------------------------------------------------------
// Persistent LSTM recurrence (R11 structure; fp16 single-precision weights)
// ---------------------------------------------------------------------------
__global__ __launch_bounds__(NTHR, 1)
void lstm_persist(const float* __restrict__ Whh, float* __restrict__ out,
                  int write_final) {
    extern __shared__ __align__(16) char smx[];
    __half* whh = (__half*)(smx + WHH_B);
    float* red = (float*)(smx + SCR_B);
    float* gb  = (float*)(smx + GB_B);
    const uint32_t sm0 = smem_u32(smx);
    const uint32_t whh_a = sm0 + WHH_B;
    const uint32_t scr_a = sm0 + SCR_B;

    const int tid = threadIdx.x;
    const int wid = tid >> 5;
    const int lane = tid & 31;
    const int base = (int)blockIdx.x * 8;
    const int ks = wid & 7;
    const int ch = wid >> 3;

    // preload W slice as fp16 [k][40] (cols 0..31 used)
    for (int it = 0; it < 64; it++) {
        int idx = tid + it * NTHR;
        int k = idx >> 5;
        int col = idx & 31;
        whh[k * 40 + col] =
            __float2half(Whh[(size_t)k * NG + (col >> 3) * NH + base + (col & 7)]);
    }

    float c_reg = 0.0f;
    unsigned bar_tgt = 0;

    __syncthreads();

    for (int t = 0; t < NT; t++) {
        // x_proj prefetch into registers (epilogue threads only)
        float xg[4];
        if (tid < 256) {
            int b = tid >> 3;
            int jj = tid & 7;
            const float* xp = g_xproj + ((size_t)b * NT + t) * NG + base + jj;
            xg[0] = xp[0];
            xg[1] = xp[NH];
            xg[2] = xp[2 * NH];
            xg[3] = xp[3 * NH];
        }

        float acc[2][2][4];
        for (int mt = 0; mt < 2; mt++)
            for (int nt = 0; nt < 2; nt++)
                for (int r = 0; r < 4; r++)
                    acc[mt][nt][r] = 0.0f;

        if (t > 0) {
            stage_h_chunk(scr_a, 0, tid);
            cp_commit();

            for (int c = 0; c < 4; c++) {
                if (c < 3) {
                    stage_h_chunk(scr_a + ((c + 1) & 1) * HBUF_STRIDE_B, c + 1,
                                  tid);
                    cp_commit();
                    cp_wait<1>();
                } else {
                    cp_wait<0>();
                }
                __syncthreads();
                rec_compute(scr_a + (c & 1) * HBUF_STRIDE_B, whh_a, c,
                            ks, ch, lane, acc);
                __syncthreads();
            }
        }

        // partials -> red (aliases staging; compute synced above)
        write_partials(red, wid, lane, acc);
        __syncthreads();

        // reduce 8 partials per col-half; thread (b = tid&31, cp = tid>>5)
        {
            int b = tid & 31;
            int cp = tid >> 5;
            int half = cp >> 3;
            float2 s = make_float2(0.0f, 0.0f);
            for (int w = 0; w < 8; w++) {
                float2 v = *(float2*)&red[(half * 8 + w) * 576 + b * 18 +
                                          ((cp * 2) & 15)];
                s.x += v.x;
                s.y += v.y;
            }
            gb[(cp * 2) * 34 + b] = s.x;
            gb[(cp * 2 + 1) * 34 + b] = s.y;
        }
        __syncthreads();

        // epilogue: thread (b, jj); c in register; write h fp32 + fp16 split
        if (tid < 256) {
            const int b = tid >> 3;
            const int jj = tid & 7;
            float gate[4];
            for (int g = 0; g < 4; g++) {
                gate[g] = gb[(g * 8 + jj) * 34 + b] + xg[g];
            }
            float ig = sigmoidf_(gate[0]);
            float fg = sigmoidf_(gate[1]);
            float gg = tanh_fast(gate[2]);
            float og = sigmoidf_(gate[3]);
            c_reg = fg * c_reg + ig * gg;
            float h = og * tanh_fast(c_reg);
            out[((size_t)b * NT + t) * NH + base + jj] = h;
            __half hh = __float2half(h);
            g_hh[b * NH + base + jj] = hh;
            g_hl[b * NH + base + jj] = __float2half(h - __half2float(hh));
            if (write_final && t == NT - 1) {
                out[HSEQ + (size_t)b * NH + base + jj] = h;
                out[HSEQ + (size_t)(NB * NH) + (size_t)b * NH + base + jj] = c_reg;
            }
        }

        // grid barrier (release/acquire; skip after last step)
        if (t < NT - 1) {
            __syncthreads();
            bar_tgt += NCTA;
            if (tid == 0) {
                red_release_add(&g_barrier, 1u);
                while (ld_acq(&g_barrier) < bar_tgt) { }
            }
            __syncthreads();
        }
    }
}

// ---------------------------------------------------------------------------
// launch
// ---------------------------------------------------------------------------
extern "C" void kernel_launch(void* const* d_in, const int* in_sizes, int n_in,
                              void* d_out, int out_size) {
    const float* x = (const float*)d_in[0];
    const float* wih = (const float*)d_in[1];
    const float* whh = (const float*)d_in[2];
    const float* bias = (const float*)d_in[3];
    float* out = (float*)d_out;

    (void)in_sizes;
    (void)n_in;

    cudaFuncSetAttribute(lstm_persist,
                         cudaFuncAttributeMaxDynamicSharedMemorySize,
                         PERSIST_SMEM);
    cudaFuncSetAttribute(mma_xproj,
                         cudaFuncAttributeMaxDynamicSharedMemorySize,
                         GEMM_SMEM);

    init_bar_kernel<<<1, 32>>>();

    split_kernel<<<((size_t)MTOT * ND) / 256, 256>>>(x, wih);

    dim3 grid(NG / 128, MTOT / 128);
    mma_xproj<<<grid, 256, GEMM_SMEM>>>(bias);

    int wf = (out_size >= (int)(HSEQ + 2 * NB * NH)) ? 1 : 0;
    lstm_persist<<<NCTA, NTHR, PERSIST_SMEM>>>(whh, out, wf);
}

// round 15
// speedup vs baseline: 1.3926x; 1.0698x over previous
#include <cuda_runtime.h>
#include <cuda_fp16.h>
#include <stdint.h>
#include <math.h>

// Problem dims
#define NB   32
#define NT   512
#define ND   1024
#define NH   1024
#define NG   4096
#define MTOT (NB * NT)
#define NCTA 128
#define NTHR 512
#define HSEQ ((size_t)NB * NT * NH)

// Scratch (allocation-free rule: __device__ globals)
__device__ float g_xproj[(size_t)MTOT * NG];            // 256 MB
__device__ unsigned g_barrier;
__device__ __half g_ah[(size_t)MTOT * ND];              // x fp16 [m][k]
__device__ __half g_bh[(size_t)ND * NG];                // wih fp16 [k][n]
__device__ __half g_hh[NB * NH];                        // h hi (per step)
__device__ __half g_hl[NB * NH];                        // h lo

// mma GEMM tile config (xproj): A single fp16, B single fp16
#define A_STRIDE 40
#define B_STRIDE 136
#define A_BUF_B (128 * A_STRIDE * 2)          // 10240
#define B_BUF_B (32 * B_STRIDE * 2)           // 8704
#define BUF_B   (A_BUF_B + B_BUF_B)           // 18944
#define GEMM_SMEM (2 * BUF_B)                 // 37888

// persistent-kernel smem byte offsets
//   whh resident fp16 [1024][40] (row 80 B = 5x16: aligned, conflict-free)
//   staging: 2 buffers of 66560 B (512-k chunk of split h:
//            hi [32][520] fp16, row 1040 B = 65x16, lo at +33280)
//   red (16 x 576 fl = 36864 B) aliases staging; gb (4352 B) disjoint
#define WHH_B  0
#define SCR_B  81920
#define HBUF_STRIDE_B 66560
#define HROW_B 1040
#define HLO_OFF 33280
#define GB_B   (SCR_B + 2 * HBUF_STRIDE_B)    // 215040
#define PERSIST_SMEM (GB_B + 4352)            // 219392

// ---------------------------------------------------------------------------
// helpers
// ---------------------------------------------------------------------------
__device__ __forceinline__ unsigned ld_acq(const unsigned* p) {
    unsigned v;
    asm volatile("ld.acquire.gpu.u32 %0, [%1];" : "=r"(v) : "l"(p) : "memory");
    return v;
}

__device__ __forceinline__ void red_release_add(unsigned* p, unsigned v) {
    asm volatile("red.release.gpu.global.add.u32 [%0], %1;"
                 :: "l"(p), "r"(v) : "memory");
}

__device__ __forceinline__ float sigmoidf_(float x) {
    return 1.0f / (1.0f + __expf(-x));
}

__device__ __forceinline__ float tanh_fast(float x) {
    float a = fabsf(x);
    float e = __expf(-2.0f * a);
    float r = (1.0f - e) / (1.0f + e);
    return copysignf(r, x);
}

__device__ __forceinline__ uint32_t smem_u32(const void* p) {
    uint32_t a;
    asm("{ .reg .u64 t; cvta.to.shared.u64 t, %1; cvt.u32.u64 %0, t; }"
        : "=r"(a) : "l"(p));
    return a;
}

__device__ __forceinline__ void cpa16(uint32_t dst, const void* src) {
    asm volatile("cp.async.ca.shared.global [%0], [%1], 16;"
                 :: "r"(dst), "l"(src));
}

__device__ __forceinline__ void cpa16_cg(uint32_t dst, const void* src) {
    asm volatile("cp.async.cg.shared.global [%0], [%1], 16;"
                 :: "r"(dst), "l"(src));
}

__device__ __forceinline__ void cp_commit() {
    asm volatile("cp.async.commit_group;");
}

template <int N>
__device__ __forceinline__ void cp_wait() {
    asm volatile("cp.async.wait_group %0;" :: "n"(N));
}

__device__ __forceinline__ void ldm_x4(uint32_t* r, uint32_t addr) {
    asm volatile("ldmatrix.sync.aligned.m8n8.x4.shared.b16 {%0,%1,%2,%3}, [%4];"
                 : "=r"(r[0]), "=r"(r[1]), "=r"(r[2]), "=r"(r[3]) : "r"(addr));
}

__device__ __forceinline__ void ldm_x4_t(uint32_t* r, uint32_t addr) {
    asm volatile("ldmatrix.sync.aligned.m8n8.x4.trans.shared.b16 {%0,%1,%2,%3}, [%4];"
                 : "=r"(r[0]), "=r"(r[1]), "=r"(r[2]), "=r"(r[3]) : "r"(addr));
}

__device__ __forceinline__ void mma_f16(float* d, const uint32_t* a,
                                        const uint32_t* b) {
    asm volatile(
        "mma.sync.aligned.m16n8k16.row.col.f32.f16.f16.f32 "
        "{%0,%1,%2,%3}, {%4,%5,%6,%7}, {%8,%9}, {%0,%1,%2,%3};"
        : "+f"(d[0]), "+f"(d[1]), "+f"(d[2]), "+f"(d[3])
        : "r"(a[0]), "r"(a[1]), "r"(a[2]), "r"(a[3]), "r"(b[0]), "r"(b[1]));
}

// ---------------------------------------------------------------------------
__global__ void init_bar_kernel() {
    if (threadIdx.x == 0) g_barrier = 0u;
}

// ---------------------------------------------------------------------------
// convert: x -> fp16, wih -> fp16
// ---------------------------------------------------------------------------
__global__ __launch_bounds__(256) void split_kernel(const float* __restrict__ x,
                                                    const float* __restrict__ wih) {
    size_t i = (size_t)blockIdx.x * blockDim.x + threadIdx.x;
    if (i < (size_t)MTOT * ND) {
        g_ah[i] = __float2half(x[i]);
    }
    if (i < (size_t)ND * NG) {
        g_bh[i] = __float2half(wih[i]);
    }
}

// ---------------------------------------------------------------------------
// x_proj = x @ W_ih + bias via fp16 mma.sync (single-term)
// ---------------------------------------------------------------------------
__device__ __forceinline__ void stage_chunk(uint32_t sbuf, int kc, int rowBase,
                                            int colBase, int tid) {
    for (int i = 0; i < 2; i++) {
        int idx = tid + i * 256;
        int row = idx >> 2;
        int c4 = idx & 3;
        size_t goff = (size_t)(rowBase + row) * ND + kc * 32 + c4 * 8;
        cpa16(sbuf + row * (A_STRIDE * 2) + c4 * 16, g_ah + goff);
    }
    for (int i = 0; i < 2; i++) {
        int idx = tid + i * 256;
        int row = idx >> 4;
        int c16 = idx & 15;
        size_t goff = (size_t)(kc * 32 + row) * NG + colBase + c16 * 8;
        cpa16(sbuf + A_BUF_B + row * (B_STRIDE * 2) + c16 * 16, g_bh + goff);
    }
}

__global__ __launch_bounds__(256) void mma_xproj(const float* __restrict__ bias) {
    extern __shared__ __align__(16) char gsm[];
    const uint32_t sb0 = smem_u32(gsm);

    const int tid = threadIdx.x;
    const int lane = tid & 31;
    const int wid = tid >> 5;
    const int warp_m = wid >> 2;
    const int warp_n = wid & 3;
    const int rowBase = blockIdx.y * 128;
    const int colBase = blockIdx.x * 128;

    float acc[4][4][4];
    for (int mt = 0; mt < 4; mt++)
        for (int nt = 0; nt < 4; nt++)
            for (int r = 0; r < 4; r++)
                acc[mt][nt][r] = 0.0f;

    stage_chunk(sb0, 0, rowBase, colBase, tid);
    cp_commit();

    for (int c = 0; c < 32; c++) {
        if (c < 31) {
            stage_chunk(sb0 + ((c + 1) & 1) * BUF_B, c + 1, rowBase, colBase, tid);
            cp_commit();
            cp_wait<1>();
        } else {
            cp_wait<0>();
        }
        __syncthreads();

        const uint32_t sb = sb0 + (c & 1) * BUF_B;
        for (int ks = 0; ks < 2; ks++) {
            uint32_t ah[4][4], bh[2][4];
            for (int mt = 0; mt < 4; mt++) {
                uint32_t ad = sb +
                    (warp_m * 64 + mt * 16 + (lane & 15)) * (A_STRIDE * 2) +
                    ks * 32 + (lane >> 4) * 16;
                ldm_x4(ah[mt], ad);
            }
            for (int np = 0; np < 2; np++) {
                uint32_t bd = sb + A_BUF_B +
                    (ks * 16 + (lane & 15)) * (B_STRIDE * 2) +
                    (warp_n * 32 + np * 16 + (lane >> 4) * 8) * 2;
                ldm_x4_t(bh[np], bd);
            }
            for (int mt = 0; mt < 4; mt++) {
                for (int np = 0; np < 2; np++) {
                    mma_f16(acc[mt][2 * np],     ah[mt], &bh[np][0]);
                    mma_f16(acc[mt][2 * np + 1], ah[mt], &bh[np][2]);
                }
            }
        }
        __syncthreads();
    }

    for (int mt = 0; mt < 4; mt++) {
        for (int nt = 0; nt < 4; nt++) {
            int row = rowBase + warp_m * 64 + mt * 16 + (lane >> 2);
            int col = colBase + warp_n * 32 + nt * 8 + (lane & 3) * 2;
            float b0 = bias[col];
            float b1 = bias[col + 1];
            float2 v0 = make_float2(acc[mt][nt][0] + b0, acc[mt][nt][1] + b1);
            float2 v1 = make_float2(acc[mt][nt][2] + b0, acc[mt][nt][3] + b1);
            *(float2*)&g_xproj[(size_t)row * NG + col] = v0;
            *(float2*)&g_xproj[(size_t)(row + 8) * NG + col] = v1;
        }
    }
}

// ---------------------------------------------------------------------------
// recurrence staging: one 512-k chunk of split h (cg = bypass L1)
// buffer: hi [32][520] fp16 (row 1040 B), lo at +33280
// ---------------------------------------------------------------------------
__device__ __forceinline__ void stage_h_chunk(uint32_t hbuf, int c, int tid) {
    int row = tid >> 4;
    int seg = tid & 15;
    const __half* srch = g_hh + row * NH + c * 512 + seg * 8;
    const __half* srcl = g_hl + row * NH + c * 512 + seg * 8;
    uint32_t d = hbuf + row * HROW_B + seg * 16;
    for (int j = 0; j < 4; j++) {
        cpa16_cg(d + j * 256, srch + j * 128);
        cpa16_cg(d + HLO_OFF + j * 256, srcl + j * 128);
    }
}

// per-warp compute for one 512-k chunk: warp = (ks 0..7: k64 slice,
// ch 0..1: col half). 4 k16 sub-slices. 2-term: (hh + hl) . w16
__device__ __forceinline__ void rec_compute(uint32_t hbuf, uint32_t wbase,
                                            int kc, int ks, int ch,
                                            int lane, float acc[2][2][4]) {
    for (int sub = 0; sub < 4; sub++) {
        uint32_t ahh[2][4], ahl[2][4], bw[4];
        for (int mt = 0; mt < 2; mt++) {
            uint32_t ad = hbuf + (mt * 16 + (lane & 15)) * HROW_B +
                          ks * 128 + sub * 32 + (lane >> 4) * 16;
            ldm_x4(ahh[mt], ad);
            ldm_x4(ahl[mt], ad + HLO_OFF);
        }
        {
            uint32_t krow = kc * 512 + ks * 64 + sub * 16 + (lane & 15);
            uint32_t coff = ch * 32 + (lane >> 4) * 16;
            ldm_x4_t(bw, wbase + krow * 80 + coff);
        }
        for (int mt = 0; mt < 2; mt++) {
            mma_f16(acc[mt][0], ahh[mt], &bw[0]);
            mma_f16(acc[mt][1], ahh[mt], &bw[2]);
            mma_f16(acc[mt][0], ahl[mt], &bw[0]);
            mma_f16(acc[mt][1], ahl[mt], &bw[2]);
        }
    }
}

// write warp partials: red[w][row 32][col 16 (+2 pad)]
__device__ __forceinline__ void write_partials(float* red, int wid, int lane,
                                               const float acc[2][2][4]) {
    float* rw = red + wid * 576;
    for (int mt = 0; mt < 2; mt++) {
        for (int nt = 0; nt < 2; nt++) {
            int row = mt * 16 + (lane >> 2);
            int col = nt * 8 + (lane & 3) * 2;
            *(float2*)&rw[row * 18 + col] =
                make_float2(acc[mt][nt][0], acc[mt][nt][1]);
            *(float2*)&rw[(row + 8) * 18 + col] =
                make_float2(acc[mt][nt][2], acc[mt][nt][3]);
        }
    }
}

// ---------------------------------------------------------------------------
// Persistent LSTM recurrence (fp16 weights, split-fp16 h, 2x512k chunks)
// ---------------------------------------------------------------------------
__global__ __launch_bounds__(NTHR, 1)
void lstm_persist(const float* __restrict__ Whh, float* __restrict__ out,
                  int write_final) {
    extern __shared__ __align__(16) char smx[];
    __half* whh = (__half*)(smx + WHH_B);
    float* red = (float*)(smx + SCR_B);
    float* gb  = (float*)(smx + GB_B);
    const uint32_t sm0 = smem_u32(smx);
    const uint32_t whh_a = sm0 + WHH_B;
    const uint32_t scr_a = sm0 + SCR_B;

    const int tid = threadIdx.x;
    const int wid = tid >> 5;
    const int lane = tid & 31;
    const int base = (int)blockIdx.x * 8;
    const int ks = wid & 7;
    const int ch = wid >> 3;

    // preload W slice as fp16 [k][40] (cols 0..31 used)
    for (int it = 0; it < 64; it++) {
        int idx = tid + it * NTHR;
        int k = idx >> 5;
        int col = idx & 31;
        whh[k * 40 + col] =
            __float2half(Whh[(size_t)k * NG + (col >> 3) * NH + base + (col & 7)]);
    }

    float c_reg = 0.0f;
    unsigned bar_tgt = 0;

    __syncthreads();

    for (int t = 0; t < NT; t++) {
        // x_proj prefetch into registers (epilogue threads only)
        float xg[4];
        if (tid < 256) {
            int b = tid >> 3;
            int jj = tid & 7;
            const float* xp = g_xproj + ((size_t)b * NT + t) * NG + base + jj;
            xg[0] = xp[0];
            xg[1] = xp[NH];
            xg[2] = xp[2 * NH];
            xg[3] = xp[3 * NH];
        }

        float acc[2][2][4];
        for (int mt = 0; mt < 2; mt++)
            for (int nt = 0; nt < 2; nt++)
                for (int r = 0; r < 4; r++)
                    acc[mt][nt][r] = 0.0f;

        if (t > 0) {
            stage_h_chunk(scr_a, 0, tid);
            cp_commit();

            for (int c = 0; c < 2; c++) {
                if (c < 1) {
                    stage_h_chunk(scr_a + HBUF_STRIDE_B, 1, tid);
                    cp_commit();
                    cp_wait<1>();
                } else {
                    cp_wait<0>();
                }
                __syncthreads();
                rec_compute(scr_a + c * HBUF_STRIDE_B, whh_a, c,
                            ks, ch, lane, acc);
                __syncthreads();
            }
        }

        // partials -> red (aliases staging buffer 0; compute synced above)
        write_partials(red, wid, lane, acc);
        __syncthreads();

        // reduce 8 partials per col-half; thread (b = tid&31, cp = tid>>5)
        {
            int b = tid & 31;
            int cp = tid >> 5;
            int half = cp >> 3;
            float2 s = make_float2(0.0f, 0.0f);
            for (int w = 0; w < 8; w++) {
                float2 v = *(float2*)&red[(half * 8 + w) * 576 + b * 18 +
                                          ((cp * 2) & 15)];
                s.x += v.x;
                s.y += v.y;
            }
            gb[(cp * 2) * 34 + b] = s.x;
            gb[(cp * 2 + 1) * 34 + b] = s.y;
        }
        __syncthreads();

        // epilogue: thread (b, jj); c in register; write h fp32 + fp16 split
        if (tid < 256) {
            const int b = tid >> 3;
            const int jj = tid & 7;
            float gate[4];
            for (int g = 0; g < 4; g++) {
                gate[g] = gb[(g * 8 + jj) * 34 + b] + xg[g];
            }
            float ig = sigmoidf_(gate[0]);
            float fg = sigmoidf_(gate[1]);
            float gg = tanh_fast(gate[2]);
            float og = sigmoidf_(gate[3]);
            c_reg = fg * c_reg + ig * gg;
            float h = og * tanh_fast(c_reg);
            out[((size_t)b * NT + t) * NH + base + jj] = h;
            __half hh = __float2half(h);
            g_hh[b * NH + base + jj] = hh;
            g_hl[b * NH + base + jj] = __float2half(h - __half2float(hh));
            if (write_final && t == NT - 1) {
                out[HSEQ + (size_t)b * NH + base + jj] = h;
                out[HSEQ + (size_t)(NB * NH) + (size_t)b * NH + base + jj] = c_reg;
            }
        }

        // grid barrier (release/acquire; skip after last step)
        if (t < NT - 1) {
            __syncthreads();
            bar_tgt += NCTA;
            if (tid == 0) {
                red_release_add(&g_barrier, 1u);
                while (ld_acq(&g_barrier) < bar_tgt) { }
            }
            __syncthreads();
        }
    }
}

// ---------------------------------------------------------------------------
// launch
// ---------------------------------------------------------------------------
extern "C" void kernel_launch(void* const* d_in, const int* in_sizes, int n_in,
                              void* d_out, int out_size) {
    const float* x = (const float*)d_in[0];
    const float* wih = (const float*)d_in[1];
    const float* whh = (const float*)d_in[2];
    const float* bias = (const float*)d_in[3];
    float* out = (float*)d_out;

    (void)in_sizes;
    (void)n_in;

    cudaFuncSetAttribute(lstm_persist,
                         cudaFuncAttributeMaxDynamicSharedMemorySize,
                         PERSIST_SMEM);
    cudaFuncSetAttribute(mma_xproj,
                         cudaFuncAttributeMaxDynamicSharedMemorySize,
                         GEMM_SMEM);

    init_bar_kernel<<<1, 32>>>();

    split_kernel<<<((size_t)MTOT * ND) / 256, 256>>>(x, wih);

    dim3 grid(NG / 128, MTOT / 128);
    mma_xproj<<<grid, 256, GEMM_SMEM>>>(bias);

    int wf = (out_size >= (int)(HSEQ + 2 * NB * NH)) ? 1 : 0;
    lstm_persist<<<NCTA, NTHR, PERSIST_SMEM>>>(whh, out, wf);
}

// round 16
// speedup vs baseline: 1.7114x; 1.2289x over previous
#include <cuda_runtime.h>
#include <cuda_fp16.h>
#include <stdint.h>
#include <math.h>

// Problem dims
#define NB   32
#define NT   512
#define ND   1024
#define NH   1024
#define NG   4096
#define MTOT (NB * NT)
#define NCTA 128
#define NTHR 512
#define HSEQ ((size_t)NB * NT * NH)

// Scratch (allocation-free rule: __device__ globals)
__device__ float g_xproj[(size_t)MTOT * NG];            // 256 MB
__device__ unsigned g_barrier;
__device__ __half g_ah[(size_t)MTOT * ND];              // x fp16 [m][k]
__device__ __half g_bh[(size_t)ND * NG];                // wih fp16 [k][n]
__device__ __half g_hh[NB * NH];                        // h fp16 (per step)

// mma GEMM tile config (xproj): BK=64, A/B single fp16
#define A_STRIDE 72                            // elements; row 144 B = 9x16
#define B_STRIDE 136                           // elements; row 272 B = 17x16
#define A_BUF_B (128 * A_STRIDE * 2)           // 18432
#define B_BUF_B (64 * B_STRIDE * 2)            // 17408
#define BUF_B   (A_BUF_B + B_BUF_B)            // 35840
#define GEMM_SMEM (2 * BUF_B)                  // 71680

// persistent-kernel smem byte offsets
//   whh resident fp16 [1024][40] (row 80 B = 5x16: aligned, conflict-free)
//   staging: 2 buffers of 33280 B (512-k chunk of h fp16:
//            [32][520], row 1040 B = 65x16)
//   red (16 x 576 fl = 36864 B) aliases both staging buffers; gb disjoint
#define WHH_B  0
#define SCR_B  81920
#define HBUF_STRIDE_B 33280
#define HROW_B 1040
#define GB_B   (SCR_B + 2 * HBUF_STRIDE_B)     // 148480
#define PERSIST_SMEM (GB_B + 4352)             // 152832

// ---------------------------------------------------------------------------
// helpers
// ---------------------------------------------------------------------------
__device__ __forceinline__ unsigned ld_acq(const unsigned* p) {
    unsigned v;
    asm volatile("ld.acquire.gpu.u32 %0, [%1];" : "=r"(v) : "l"(p) : "memory");
    return v;
}

__device__ __forceinline__ void red_release_add(unsigned* p, unsigned v) {
    asm volatile("red.release.gpu.global.add.u32 [%0], %1;"
                 :: "l"(p), "r"(v) : "memory");
}

__device__ __forceinline__ float sigmoidf_(float x) {
    return 1.0f / (1.0f + __expf(-x));
}

__device__ __forceinline__ float tanh_fast(float x) {
    float a = fabsf(x);
    float e = __expf(-2.0f * a);
    float r = (1.0f - e) / (1.0f + e);
    return copysignf(r, x);
}

__device__ __forceinline__ uint32_t smem_u32(const void* p) {
    uint32_t a;
    asm("{ .reg .u64 t; cvta.to.shared.u64 t, %1; cvt.u32.u64 %0, t; }"
        : "=r"(a) : "l"(p));
    return a;
}

__device__ __forceinline__ void cpa16(uint32_t dst, const void* src) {
    asm volatile("cp.async.ca.shared.global [%0], [%1], 16;"
                 :: "r"(dst), "l"(src));
}

__device__ __forceinline__ void cpa16_cg(uint32_t dst, const void* src) {
    asm volatile("cp.async.cg.shared.global [%0], [%1], 16;"
                 :: "r"(dst), "l"(src));
}

__device__ __forceinline__ void cp_commit() {
    asm volatile("cp.async.commit_group;");
}

template <int N>
__device__ __forceinline__ void cp_wait() {
    asm volatile("cp.async.wait_group %0;" :: "n"(N));
}

__device__ __forceinline__ void ldm_x4(uint32_t* r, uint32_t addr) {
    asm volatile("ldmatrix.sync.aligned.m8n8.x4.shared.b16 {%0,%1,%2,%3}, [%4];"
                 : "=r"(r[0]), "=r"(r[1]), "=r"(r[2]), "=r"(r[3]) : "r"(addr));
}

__device__ __forceinline__ void ldm_x4_t(uint32_t* r, uint32_t addr) {
    asm volatile("ldmatrix.sync.aligned.m8n8.x4.trans.shared.b16 {%0,%1,%2,%3}, [%4];"
                 : "=r"(r[0]), "=r"(r[1]), "=r"(r[2]), "=r"(r[3]) : "r"(addr));
}

__device__ __forceinline__ void mma_f16(float* d, const uint32_t* a,
                                        const uint32_t* b) {
    asm volatile(
        "mma.sync.aligned.m16n8k16.row.col.f32.f16.f16.f32 "
        "{%0,%1,%2,%3}, {%4,%5,%6,%7}, {%8,%9}, {%0,%1,%2,%3};"
        : "+f"(d[0]), "+f"(d[1]), "+f"(d[2]), "+f"(d[3])
        : "r"(a[0]), "r"(a[1]), "r"(a[2]), "r"(a[3]), "r"(b[0]), "r"(b[1]));
}

// ---------------------------------------------------------------------------
__global__ void init_bar_kernel() {
    if (threadIdx.x == 0) g_barrier = 0u;
}

// ---------------------------------------------------------------------------
// convert: x -> fp16, wih -> fp16
// ---------------------------------------------------------------------------
__global__ __launch_bounds__(256) void split_kernel(const float* __restrict__ x,
                                                    const float* __restrict__ wih) {
    size_t i = (size_t)blockIdx.x * blockDim.x + threadIdx.x;
    if (i < (size_t)MTOT * ND) {
        g_ah[i] = __float2half(x[i]);
    }
    if (i < (size_t)ND * NG) {
        g_bh[i] = __float2half(wih[i]);
    }
}

// ---------------------------------------------------------------------------
// x_proj = x @ W_ih + bias via fp16 mma.sync, BK=64 double-buffered
// ---------------------------------------------------------------------------
__device__ __forceinline__ void stage_chunk(uint32_t sbuf, int kc, int rowBase,
                                            int colBase, int tid) {
    for (int i = 0; i < 4; i++) {
        int idx = tid + i * 256;          // 0..1023
        int row = idx >> 3;               // 0..127
        int seg = idx & 7;                // 8 x 16B per 128B of data
        size_t goff = (size_t)(rowBase + row) * ND + kc * 64 + seg * 8;
        cpa16(sbuf + row * (A_STRIDE * 2) + seg * 16, g_ah + goff);
    }
    for (int i = 0; i < 4; i++) {
        int idx = tid + i * 256;          // 0..1023
        int row = idx >> 4;               // 0..63
        int c16 = idx & 15;
        size_t goff = (size_t)(kc * 64 + row) * NG + colBase + c16 * 8;
        cpa16(sbuf + A_BUF_B + row * (B_STRIDE * 2) + c16 * 16, g_bh + goff);
    }
}

__global__ __launch_bounds__(256) void mma_xproj(const float* __restrict__ bias) {
    extern __shared__ __align__(16) char gsm[];
    const uint32_t sb0 = smem_u32(gsm);

    const int tid = threadIdx.x;
    const int lane = tid & 31;
    const int wid = tid >> 5;
    const int warp_m = wid >> 2;
    const int warp_n = wid & 3;
    const int rowBase = blockIdx.y * 128;
    const int colBase = blockIdx.x * 128;

    float acc[4][4][4];
    for (int mt = 0; mt < 4; mt++)
        for (int nt = 0; nt < 4; nt++)
            for (int r = 0; r < 4; r++)
                acc[mt][nt][r] = 0.0f;

    stage_chunk(sb0, 0, rowBase, colBase, tid);
    cp_commit();

    for (int c = 0; c < 16; c++) {
        if (c < 15) {
            stage_chunk(sb0 + ((c + 1) & 1) * BUF_B, c + 1, rowBase, colBase, tid);
            cp_commit();
            cp_wait<1>();
        } else {
            cp_wait<0>();
        }
        __syncthreads();

        const uint32_t sb = sb0 + (c & 1) * BUF_B;
        for (int ks = 0; ks < 4; ks++) {
            uint32_t ah[4][4], bh[2][4];
            for (int mt = 0; mt < 4; mt++) {
                uint32_t ad = sb +
                    (warp_m * 64 + mt * 16 + (lane & 15)) * (A_STRIDE * 2) +
                    ks * 32 + (lane >> 4) * 16;
                ldm_x4(ah[mt], ad);
            }
            for (int np = 0; np < 2; np++) {
                uint32_t bd = sb + A_BUF_B +
                    (ks * 16 + (lane & 15)) * (B_STRIDE * 2) +
                    (warp_n * 32 + np * 16 + (lane >> 4) * 8) * 2;
                ldm_x4_t(bh[np], bd);
            }
            for (int mt = 0; mt < 4; mt++) {
                for (int np = 0; np < 2; np++) {
                    mma_f16(acc[mt][2 * np],     ah[mt], &bh[np][0]);
                    mma_f16(acc[mt][2 * np + 1], ah[mt], &bh[np][2]);
                }
            }
        }
        __syncthreads();
    }

    for (int mt = 0; mt < 4; mt++) {
        for (int nt = 0; nt < 4; nt++) {
            int row = rowBase + warp_m * 64 + mt * 16 + (lane >> 2);
            int col = colBase + warp_n * 32 + nt * 8 + (lane & 3) * 2;
            float b0 = bias[col];
            float b1 = bias[col + 1];
            float2 v0 = make_float2(acc[mt][nt][0] + b0, acc[mt][nt][1] + b1);
            float2 v1 = make_float2(acc[mt][nt][2] + b0, acc[mt][nt][3] + b1);
            *(float2*)&g_xproj[(size_t)row * NG + col] = v0;
            *(float2*)&g_xproj[(size_t)(row + 8) * NG + col] = v1;
        }
    }
}

// ---------------------------------------------------------------------------
// recurrence staging: one 512-k chunk of h fp16 (cg = bypass L1)
// buffer: [32][520] fp16, row 1040 B
// ---------------------------------------------------------------------------
__device__ __forceinline__ void stage_h_chunk(uint32_t hbuf, int c, int tid) {
    int row = tid >> 4;
    int seg = tid & 15;
    const __half* srch = g_hh + row * NH + c * 512 + seg * 8;
    uint32_t d = hbuf + row * HROW_B + seg * 16;
    for (int j = 0; j < 4; j++) {
        cpa16_cg(d + j * 256, srch + j * 128);
    }
}

// per-warp compute for one 512-k chunk: warp = (ks 0..7: k64 slice,
// ch 0..1: col half). 4 k16 sub-slices; single-term h . w16
__device__ __forceinline__ void rec_compute(uint32_t hbuf, uint32_t wbase,
                                            int kc, int ks, int ch,
                                            int lane, float acc[2][2][4]) {
    for (int sub = 0; sub < 4; sub++) {
        uint32_t ahh[2][4], bw[4];
        for (int mt = 0; mt < 2; mt++) {
            uint32_t ad = hbuf + (mt * 16 + (lane & 15)) * HROW_B +
                          ks * 128 + sub * 32 + (lane >> 4) * 16;
            ldm_x4(ahh[mt], ad);
        }
        {
            uint32_t krow = kc * 512 + ks * 64 + sub * 16 + (lane & 15);
            uint32_t coff = ch * 32 + (lane >> 4) * 16;
            ldm_x4_t(bw, wbase + krow * 80 + coff);
        }
        for (int mt = 0; mt < 2; mt++) {
            mma_f16(acc[mt][0], ahh[mt], &bw[0]);
            mma_f16(acc[mt][1], ahh[mt], &bw[2]);
        }
    }
}

// write warp partials: red[w][row 32][col 16 (+2 pad)]
__device__ __forceinline__ void write_partials(float* red, int wid, int lane,
                                               const float acc[2][2][4]) {
    float* rw = red + wid * 576;
    for (int mt = 0; mt < 2; mt++) {
        for (int nt = 0; nt < 2; nt++) {
            int row = mt * 16 + (lane >> 2);
            int col = nt * 8 + (lane & 3) * 2;
            *(float2*)&rw[row * 18 + col] =
                make_float2(acc[mt][nt][0], acc[mt][nt][1]);
            *(float2*)&rw[(row + 8) * 18 + col] =
                make_float2(acc[mt][nt][2], acc[mt][nt][3]);
        }
    }
}

// ---------------------------------------------------------------------------
// Persistent LSTM recurrence (fp16 weights, fp16 h, 2x512k chunks)
// ---------------------------------------------------------------------------
__global__ __launch_bounds__(NTHR, 1)
void lstm_persist(const float* __restrict__ Whh, float* __restrict__ out,
                  int write_final) {
    extern __shared__ __align__(16) char smx[];
    __half* whh = (__half*)(smx + WHH_B);
    float* red = (float*)(smx + SCR_B);
    float* gb  = (float*)(smx + GB_B);
    const uint32_t sm0 = smem_u32(smx);
    const uint32_t whh_a = sm0 + WHH_B;
    const uint32_t scr_a = sm0 + SCR_B;

    const int tid = threadIdx.x;
    const int wid = tid >> 5;
    const int lane = tid & 31;
    const int base = (int)blockIdx.x * 8;
    const int ks = wid & 7;
    const int ch = wid >> 3;

    // preload W slice as fp16 [k][40] (cols 0..31 used)
    for (int it = 0; it < 64; it++) {
        int idx = tid + it * NTHR;
        int k = idx >> 5;
        int col = idx & 31;
        whh[k * 40 + col] =
            __float2half(Whh[(size_t)k * NG + (col >> 3) * NH + base + (col & 7)]);
    }

    float c_reg = 0.0f;
    unsigned bar_tgt = 0;

    __syncthreads();

    for (int t = 0; t < NT; t++) {
        // x_proj prefetch into registers (epilogue threads only)
        float xg[4];
        if (tid < 256) {
            int b = tid >> 3;
            int jj = tid & 7;
            const float* xp = g_xproj + ((size_t)b * NT + t) * NG + base + jj;
            xg[0] = xp[0];
            xg[1] = xp[NH];
            xg[2] = xp[2 * NH];
            xg[3] = xp[3 * NH];
        }

        float acc[2][2][4];
        for (int mt = 0; mt < 2; mt++)
            for (int nt = 0; nt < 2; nt++)
                for (int r = 0; r < 4; r++)
                    acc[mt][nt][r] = 0.0f;

        if (t > 0) {
            stage_h_chunk(scr_a, 0, tid);
            cp_commit();

            for (int c = 0; c < 2; c++) {
                if (c < 1) {
                    stage_h_chunk(scr_a + HBUF_STRIDE_B, 1, tid);
                    cp_commit();
                    cp_wait<1>();
                } else {
                    cp_wait<0>();
                }
                __syncthreads();
                rec_compute(scr_a + c * HBUF_STRIDE_B, whh_a, c,
                            ks, ch, lane, acc);
                __syncthreads();
            }
        }

        // partials -> red (aliases staging buffers; compute synced above)
        write_partials(red, wid, lane, acc);
        __syncthreads();

        // reduce 8 partials per col-half; thread (b = tid&31, cp = tid>>5)
        {
            int b = tid & 31;
            int cp = tid >> 5;
            int half = cp >> 3;
            float2 s = make_float2(0.0f, 0.0f);
            for (int w = 0; w < 8; w++) {
                float2 v = *(float2*)&red[(half * 8 + w) * 576 + b * 18 +
                                          ((cp * 2) & 15)];
                s.x += v.x;
                s.y += v.y;
            }
            gb[(cp * 2) * 34 + b] = s.x;
            gb[(cp * 2 + 1) * 34 + b] = s.y;
        }
        __syncthreads();

        // epilogue: thread (b, jj); c in register; write h fp32 + fp16
        if (tid < 256) {
            const int b = tid >> 3;
            const int jj = tid & 7;
            float gate[4];
            for (int g = 0; g < 4; g++) {
                gate[g] = gb[(g * 8 + jj) * 34 + b] + xg[g];
            }
            float ig = sigmoidf_(gate[0]);
            float fg = sigmoidf_(gate[1]);
            float gg = tanh_fast(gate[2]);
            float og = sigmoidf_(gate[3]);
            c_reg = fg * c_reg + ig * gg;
            float h = og * tanh_fast(c_reg);
            out[((size_t)b * NT + t) * NH + base + jj] = h;
            g_hh[b * NH + base + jj] = __float2half(h);
            if (write_final && t == NT - 1) {
                out[HSEQ + (size_t)b * NH + base + jj] = h;
                out[HSEQ + (size_t)(NB * NH) + (size_t)b * NH + base + jj] = c_reg;
            }
        }

        // grid barrier (release/acquire; skip after last step)
        if (t < NT - 1) {
            __syncthreads();
            bar_tgt += NCTA;
            if (tid == 0) {
                red_release_add(&g_barrier, 1u);
                while (ld_acq(&g_barrier) < bar_tgt) { }
            }
            __syncthreads();
        }
    }
}

// ---------------------------------------------------------------------------
// launch
// ---------------------------------------------------------------------------
extern "C" void kernel_launch(void* const* d_in, const int* in_sizes, int n_in,
                              void* d_out, int out_size) {
    const float* x = (const float*)d_in[0];
    const float* wih = (const float*)d_in[1];
    const float* whh = (const float*)d_in[2];
    const float* bias = (const float*)d_in[3];
    float* out = (float*)d_out;

    (void)in_sizes;
    (void)n_in;

    cudaFuncSetAttribute(lstm_persist,
                         cudaFuncAttributeMaxDynamicSharedMemorySize,
                         PERSIST_SMEM);
    cudaFuncSetAttribute(mma_xproj,
                         cudaFuncAttributeMaxDynamicSharedMemorySize,
                         GEMM_SMEM);

    init_bar_kernel<<<1, 32>>>();

    split_kernel<<<((size_t)MTOT * ND) / 256, 256>>>(x, wih);

    dim3 grid(NG / 128, MTOT / 128);
    mma_xproj<<<grid, 256, GEMM_SMEM>>>(bias);

    int wf = (out_size >= (int)(HSEQ + 2 * NB * NH)) ? 1 : 0;
    lstm_persist<<<NCTA, NTHR, PERSIST_SMEM>>>(whh, out, wf);
}